// round 3
// baseline (speedup 1.0000x reference)
#include <cuda_runtime.h>

// Problem constants
#define I_ 3
#define H_ 2048
#define O_ 2
#define R_ 2
#define S_ 4
#define G_ 7
#define B_ 32
#define T_ 512
#define ALPHA_ 0.2f
#define DECAY_ 0.8f
#define NSTD_ 0.05f

#define NTHREADS 256
#define NWARPS (NTHREADS / 32)   // 8
#define EPT 8                    // 256*8 = 2048 = H

__device__ __forceinline__ float fast_tanh(float x) {
    // tanh(x) = 1 - 2/(1+exp(2x)); matched R1's rel_err=6e-6
    float e = __expf(2.0f * x);
    return 1.0f - __fdividef(2.0f, 1.0f + e);
}

// ---------------------------------------------------------------------------
// 4-channel block reduction with channel folding.
// Input: per-thread partials p = (x, y, z, w).
// Output: every thread gets Sx (=sum of x) and Sy; warp 0 additionally
// resolves Sz, Sw (written to *oz/*ow, valid in warp 0 only).
// One __syncthreads() per call; alternate `buf`.
// Channel permutation after folding: lane&3 == 0->x, 1->z, 2->y, 3->w.
// ---------------------------------------------------------------------------
__device__ __forceinline__ void block_reduce4_folded(
    float4 p, float* s_red /* [2][NWARPS*4] */, int buf, int warp, int lane,
    float& Sx, float& Sy, float& Sz_w0, float& Sw_w0)
{
    const unsigned FULL = 0xffffffffu;
    const bool k1 = !(lane & 1);
    // level 1 (xor 1): fold 4 channels -> 2 per lane
    float sA = k1 ? p.z : p.x;
    float rA = __shfl_xor_sync(FULL, sA, 1);
    float v0 = (k1 ? p.x : p.z) + rA;
    float sB = k1 ? p.w : p.y;
    float rB = __shfl_xor_sync(FULL, sB, 1);
    float v1 = (k1 ? p.y : p.w) + rB;
    // level 2 (xor 2): fold 2 -> 1
    const bool k2 = !(lane & 2);
    float sC = k2 ? v1 : v0;
    float rC = __shfl_xor_sync(FULL, sC, 2);
    float v  = (k2 ? v0 : v1) + rC;
    // levels 3..5: plain butterfly, channel preserved (channel = perm(lane&3))
    v += __shfl_xor_sync(FULL, v, 4);
    v += __shfl_xor_sync(FULL, v, 8);
    v += __shfl_xor_sync(FULL, v, 16);

    // lanes 0..3 publish warp partials
    if (lane < 4) s_red[buf * (NWARPS * 4) + warp * 4 + lane] = v;
    __syncthreads();

    // level 2 across warps: NWARPS*4 = 32 values, butterfly over warp bits
    float u = s_red[buf * (NWARPS * 4) + lane];
    u += __shfl_xor_sync(FULL, u, 4);
    u += __shfl_xor_sync(FULL, u, 8);
    u += __shfl_xor_sync(FULL, u, 16);
    // lane&3: 0 -> x, 1 -> z, 2 -> y, 3 -> w
    Sx = __shfl_sync(FULL, u, 0);
    Sy = __shfl_sync(FULL, u, 2);
    if (warp == 0) {
        Sz_w0 = __shfl_sync(FULL, u, 1);
        Sw_w0 = __shfl_sync(FULL, u, 3);
    }
}

__global__ __launch_bounds__(NTHREADS, 1)
void lowrank_rnn_kernel(const float* __restrict__ input,   // (B,T,I)
                        const float* __restrict__ noise,   // (B,T,H)
                        const float* __restrict__ wi,      // (I,S,G)
                        const float* __restrict__ unitwi,  // (I,S,1)
                        const float* __restrict__ m,       // (R,S,G)
                        const float* __restrict__ n,       // (R,S,G)
                        const float* __restrict__ unitm,   // (R,S,1)
                        const float* __restrict__ unitn,   // (R,S,1)
                        const float* __restrict__ wo,      // (O,S,G)
                        const float* __restrict__ h0,      // (S,G)
                        const float* __restrict__ unith0,  // (S,1)
                        const float* __restrict__ bias,    // (S,1)
                        const float* __restrict__ gb,      // (G,H)
                        const float* __restrict__ uv,      // (1,H)
                        const float* __restrict__ sup,     // (S,H)
                        float* __restrict__ out)           // out(B,T,O) ++ traj(B,T,H)
{
    const int b    = blockIdx.x;
    const int tid  = threadIdx.x;
    const int lane = tid & 31;
    const int warp = tid >> 5;

    __shared__ float s_red[2 * NWARPS * 4];

    // ------------------------------------------------------------------
    // Phase 1: per-element effective weights in registers (one-time).
    // ALPHA folded into c_m* / c_wi* so the hot loop is pure FMA.
    // ------------------------------------------------------------------
    float hreg[EPT];
    float c_m0[EPT], c_m1[EPT], c_n0[EPT], c_n1[EPT];
    float c_wo0[EPT], c_wo1[EPT], c_bias[EPT];
    float c_wi0[EPT], c_wi1[EPT], c_wi2[EPT];

#pragma unroll
    for (int e = 0; e < EPT; e++) {
        const int hidx = tid * EPT + e;
        float gvec[G_];
#pragma unroll
        for (int g = 0; g < G_; g++) gvec[g] = gb[g * H_ + hidx];
        const float uvh = uv[hidx];

        float awi0 = 0.f, awi1 = 0.f, awi2 = 0.f;
        float am0 = 0.f, am1 = 0.f, an0 = 0.f, an1 = 0.f;
        float awo0 = 0.f, awo1 = 0.f, ah0 = 0.f, ab = 0.f;

#pragma unroll
        for (int s = 0; s < S_; s++) {
            const float su = sup[s * H_ + hidx];

            float d0 = 0.f, d1 = 0.f, d2 = 0.f;
#pragma unroll
            for (int g = 0; g < G_; g++) {
                d0 += wi[(0 * S_ + s) * G_ + g] * gvec[g];
                d1 += wi[(1 * S_ + s) * G_ + g] * gvec[g];
                d2 += wi[(2 * S_ + s) * G_ + g] * gvec[g];
            }
            awi0 += (d0 + unitwi[0 * S_ + s] * uvh) * su;
            awi1 += (d1 + unitwi[1 * S_ + s] * uvh) * su;
            awi2 += (d2 + unitwi[2 * S_ + s] * uvh) * su;

            float dm0 = 0.f, dm1 = 0.f, dn0 = 0.f, dn1 = 0.f;
#pragma unroll
            for (int g = 0; g < G_; g++) {
                dm0 += m[(0 * S_ + s) * G_ + g] * gvec[g];
                dm1 += m[(1 * S_ + s) * G_ + g] * gvec[g];
                dn0 += n[(0 * S_ + s) * G_ + g] * gvec[g];
                dn1 += n[(1 * S_ + s) * G_ + g] * gvec[g];
            }
            am0 += (dm0 + unitm[0 * S_ + s] * uvh) * su;
            am1 += (dm1 + unitm[1 * S_ + s] * uvh) * su;
            an0 += (dn0 + unitn[0 * S_ + s] * uvh) * su;
            an1 += (dn1 + unitn[1 * S_ + s] * uvh) * su;

            float do0 = 0.f, do1 = 0.f, dh = 0.f;
#pragma unroll
            for (int g = 0; g < G_; g++) {
                do0 += wo[(0 * S_ + s) * G_ + g] * gvec[g];
                do1 += wo[(1 * S_ + s) * G_ + g] * gvec[g];
                dh  += h0[s * G_ + g] * gvec[g];
            }
            awo0 += do0 * su;
            awo1 += do1 * su;
            ah0  += dh * su + unith0[s] * uvh * su;
            ab   += bias[s] * uvh * su;
        }
        hreg[e]  = ah0;
        c_m0[e]  = ALPHA_ * am0;  c_m1[e]  = ALPHA_ * am1;
        c_n0[e]  = an0;           c_n1[e]  = an1;
        c_wo0[e] = awo0;          c_wo1[e] = awo1;
        c_bias[e] = ab;
        c_wi0[e] = ALPHA_ * awi0; c_wi1[e] = ALPHA_ * awi1;
        c_wi2[e] = ALPHA_ * awi2;
    }

    // ------------------------------------------------------------------
    // Phase 2: recurrence with one fused 4-channel reduction per step.
    // ------------------------------------------------------------------
    const float* zb = noise + (size_t)b * T_ * H_;
    const float* xb = input + (size_t)b * T_ * I_;
    float* outp  = out + (size_t)b * T_ * O_;
    float* trajp = out + (size_t)B_ * T_ * O_ + (size_t)b * T_ * H_;

    // Initial reduction: Sn from r0 = tanh(h0)
    float Sn0, Sn1, dum0, dum1;
    {
        float4 p = make_float4(0.f, 0.f, 0.f, 0.f);
#pragma unroll
        for (int e = 0; e < EPT; e++) {
            float r = fast_tanh(hreg[e]);
            p.x = fmaf(r, c_n0[e], p.x);
            p.y = fmaf(r, c_n1[e], p.y);
        }
        block_reduce4_folded(p, s_red, 0, warp, lane, Sn0, Sn1, dum0, dum1);
    }

    // Prefetch noise / input two steps ahead
    float4 z0a = *(const float4*)(zb + 0 * (size_t)H_ + tid * EPT);
    float4 z0b = *(const float4*)(zb + 0 * (size_t)H_ + tid * EPT + 4);
    float4 z1a = *(const float4*)(zb + 1 * (size_t)H_ + tid * EPT);
    float4 z1b = *(const float4*)(zb + 1 * (size_t)H_ + tid * EPT + 4);
    float xA0 = xb[0], xA1 = xb[1], xA2 = xb[2];
    float xB0 = xb[3], xB1 = xb[4], xB2 = xb[5];

    for (int t = 0; t < T_; t++) {
        const int tp = (t + 2 < T_) ? (t + 2) : (T_ - 1);
        float4 z2a = *(const float4*)(zb + (size_t)tp * H_ + tid * EPT);
        float4 z2b = *(const float4*)(zb + (size_t)tp * H_ + tid * EPT + 4);
        const float xC0 = xb[tp * I_ + 0];
        const float xC1 = xb[tp * I_ + 1];
        const float xC2 = xb[tp * I_ + 2];

        const float zarr[EPT] = {z0a.x, z0a.y, z0a.z, z0a.w,
                                 z0b.x, z0b.y, z0b.z, z0b.w};
        float4 pr = make_float4(0.f, 0.f, 0.f, 0.f);
        float hnew[EPT];
#pragma unroll
        for (int e = 0; e < EPT; e++) {
            float h = hreg[e];
            h = fmaf(h, DECAY_, c_bias[e]);
            h = fmaf(zarr[e], NSTD_, h);
            h = fmaf(Sn0, c_m0[e], h);
            h = fmaf(Sn1, c_m1[e], h);
            h = fmaf(xA0, c_wi0[e], h);
            h = fmaf(xA1, c_wi1[e], h);
            h = fmaf(xA2, c_wi2[e], h);
            hreg[e] = h;
            hnew[e] = h;
            float r = fast_tanh(h);
            pr.x = fmaf(r, c_n0[e], pr.x);
            pr.y = fmaf(r, c_n1[e], pr.y);
            pr.z = fmaf(r, c_wo0[e], pr.z);
            pr.w = fmaf(r, c_wo1[e], pr.w);
        }
        // stream traj
        *(float4*)(trajp + (size_t)t * H_ + tid * EPT) =
            make_float4(hnew[0], hnew[1], hnew[2], hnew[3]);
        *(float4*)(trajp + (size_t)t * H_ + tid * EPT + 4) =
            make_float4(hnew[4], hnew[5], hnew[6], hnew[7]);

        float o0, o1;
        block_reduce4_folded(pr, s_red, (t + 1) & 1, warp, lane,
                             Sn0, Sn1, o0, o1);
        if (warp == 0 && lane == 0) {
            outp[t * O_ + 0] = o0;
            outp[t * O_ + 1] = o1;
        }

        z0a = z1a; z0b = z1b;
        z1a = z2a; z1b = z2b;
        xA0 = xB0; xA1 = xB1; xA2 = xB2;
        xB0 = xC0; xB1 = xC1; xB2 = xC2;
    }
}

extern "C" void kernel_launch(void* const* d_in, const int* in_sizes, int n_in,
                              void* d_out, int out_size) {
    (void)in_sizes; (void)n_in; (void)out_size;
    const float* input    = (const float*)d_in[0];
    const float* noise    = (const float*)d_in[1];
    const float* wi       = (const float*)d_in[2];
    const float* unitwi   = (const float*)d_in[3];
    const float* m        = (const float*)d_in[4];
    const float* n        = (const float*)d_in[5];
    const float* unitm    = (const float*)d_in[6];
    const float* unitn    = (const float*)d_in[7];
    const float* wo       = (const float*)d_in[8];
    const float* h0       = (const float*)d_in[9];
    const float* unith0   = (const float*)d_in[10];
    const float* bias     = (const float*)d_in[11];
    const float* gb       = (const float*)d_in[12];
    const float* uv       = (const float*)d_in[13];
    const float* sup      = (const float*)d_in[14];
    float* out            = (float*)d_out;

    lowrank_rnn_kernel<<<B_, NTHREADS>>>(input, noise, wi, unitwi, m, n, unitm,
                                         unitn, wo, h0, unith0, bias, gb, uv,
                                         sup, out);
}

// round 4
// speedup vs baseline: 1.3724x; 1.3724x over previous
#include <cuda_runtime.h>

// Problem constants
#define I_ 3
#define H_ 2048
#define O_ 2
#define R_ 2
#define S_ 4
#define G_ 7
#define B_ 32
#define T_ 512
#define ALPHA_ 0.2f
#define DECAY_ 0.8f
#define NSTD_ 0.05f

#define NTHREADS 512
#define NWARPS (NTHREADS / 32)   // 16
#define EPT 4                    // 512*4 = 2048 = H
#define NPART (NWARPS * 4)       // 64 partials per buffer

__device__ __forceinline__ float fast_tanh(float x) {
    float e = __expf(2.0f * x);
    return 1.0f - __fdividef(2.0f, 1.0f + e);
}

__global__ __launch_bounds__(NTHREADS, 1)
void lowrank_rnn_kernel(const float* __restrict__ input,   // (B,T,I)
                        const float* __restrict__ noise,   // (B,T,H)
                        const float* __restrict__ wi,      // (I,S,G)
                        const float* __restrict__ unitwi,  // (I,S,1)
                        const float* __restrict__ m,       // (R,S,G)
                        const float* __restrict__ n,       // (R,S,G)
                        const float* __restrict__ unitm,   // (R,S,1)
                        const float* __restrict__ unitn,   // (R,S,1)
                        const float* __restrict__ wo,      // (O,S,G)
                        const float* __restrict__ h0,      // (S,G)
                        const float* __restrict__ unith0,  // (S,1)
                        const float* __restrict__ bias,    // (S,1)
                        const float* __restrict__ gb,      // (G,H)
                        const float* __restrict__ uv,      // (1,H)
                        const float* __restrict__ sup,     // (S,H)
                        float* __restrict__ out)           // out(B,T,O) ++ traj(B,T,H)
{
    const int b    = blockIdx.x;
    const int tid  = threadIdx.x;
    const int lane = tid & 31;
    const int warp = tid >> 5;
    const unsigned FULL = 0xffffffffu;

    __shared__ float s_red[2 * NPART];

    // ------------------------------------------------------------------
    // Phase 1: per-element effective weights in registers (one-time).
    // ALPHA folded into c_m* / c_wi*.
    // ------------------------------------------------------------------
    float hreg[EPT];
    float c_m0[EPT], c_m1[EPT], c_n0[EPT], c_n1[EPT];
    float c_wo0[EPT], c_wo1[EPT], c_bias[EPT];
    float c_wi0[EPT], c_wi1[EPT], c_wi2[EPT];

#pragma unroll
    for (int e = 0; e < EPT; e++) {
        const int hidx = tid * EPT + e;
        float gvec[G_];
#pragma unroll
        for (int g = 0; g < G_; g++) gvec[g] = gb[g * H_ + hidx];
        const float uvh = uv[hidx];

        float awi0 = 0.f, awi1 = 0.f, awi2 = 0.f;
        float am0 = 0.f, am1 = 0.f, an0 = 0.f, an1 = 0.f;
        float awo0 = 0.f, awo1 = 0.f, ah0 = 0.f, ab = 0.f;

#pragma unroll
        for (int s = 0; s < S_; s++) {
            const float su = sup[s * H_ + hidx];

            float d0 = 0.f, d1 = 0.f, d2 = 0.f;
#pragma unroll
            for (int g = 0; g < G_; g++) {
                d0 += wi[(0 * S_ + s) * G_ + g] * gvec[g];
                d1 += wi[(1 * S_ + s) * G_ + g] * gvec[g];
                d2 += wi[(2 * S_ + s) * G_ + g] * gvec[g];
            }
            awi0 += (d0 + unitwi[0 * S_ + s] * uvh) * su;
            awi1 += (d1 + unitwi[1 * S_ + s] * uvh) * su;
            awi2 += (d2 + unitwi[2 * S_ + s] * uvh) * su;

            float dm0 = 0.f, dm1 = 0.f, dn0 = 0.f, dn1 = 0.f;
#pragma unroll
            for (int g = 0; g < G_; g++) {
                dm0 += m[(0 * S_ + s) * G_ + g] * gvec[g];
                dm1 += m[(1 * S_ + s) * G_ + g] * gvec[g];
                dn0 += n[(0 * S_ + s) * G_ + g] * gvec[g];
                dn1 += n[(1 * S_ + s) * G_ + g] * gvec[g];
            }
            am0 += (dm0 + unitm[0 * S_ + s] * uvh) * su;
            am1 += (dm1 + unitm[1 * S_ + s] * uvh) * su;
            an0 += (dn0 + unitn[0 * S_ + s] * uvh) * su;
            an1 += (dn1 + unitn[1 * S_ + s] * uvh) * su;

            float do0 = 0.f, do1 = 0.f, dh = 0.f;
#pragma unroll
            for (int g = 0; g < G_; g++) {
                do0 += wo[(0 * S_ + s) * G_ + g] * gvec[g];
                do1 += wo[(1 * S_ + s) * G_ + g] * gvec[g];
                dh  += h0[s * G_ + g] * gvec[g];
            }
            awo0 += do0 * su;
            awo1 += do1 * su;
            ah0  += dh * su + unith0[s] * uvh * su;
            ab   += bias[s] * uvh * su;
        }
        hreg[e]  = ah0;
        c_m0[e]  = ALPHA_ * am0;  c_m1[e]  = ALPHA_ * am1;
        c_n0[e]  = an0;           c_n1[e]  = an1;
        c_wo0[e] = awo0;          c_wo1[e] = awo1;
        c_bias[e] = ab;
        c_wi0[e] = ALPHA_ * awi0; c_wi1[e] = ALPHA_ * awi1;
        c_wi2[e] = ALPHA_ * awi2;
    }

    // ------------------------------------------------------------------
    // Phase 2: recurrence, software-pipelined.
    // Invariant at loop top: hreg = h_t, pr = 4-ch partials of r_t=tanh(h_t)
    //   channels (x=n0, y=n1, z=wo0, w=wo1).
    // Iter t: reduce pr -> Sn_t (writes out[t-1]), h_{t+1} = base + Sn·m,
    //   traj[t] = h_{t+1}, pr := partials of r_{t+1}.
    // ------------------------------------------------------------------
    const float* zb = noise + (size_t)b * T_ * H_;
    const float* xb = input + (size_t)b * T_ * I_;
    float* outp  = out + (size_t)b * T_ * O_;
    float* trajp = out + (size_t)B_ * T_ * O_ + (size_t)b * T_ * H_;

    // pr for r_0 = tanh(h_0)
    float4 pr = make_float4(0.f, 0.f, 0.f, 0.f);
#pragma unroll
    for (int e = 0; e < EPT; e++) {
        float r = fast_tanh(hreg[e]);
        pr.x = fmaf(r, c_n0[e], pr.x);
        pr.y = fmaf(r, c_n1[e], pr.y);
        pr.z = fmaf(r, c_wo0[e], pr.z);
        pr.w = fmaf(r, c_wo1[e], pr.w);
    }

    // Prefetch noise / input two steps ahead
    float4 z0 = *(const float4*)(zb + 0 * (size_t)H_ + tid * 4);
    float4 z1 = *(const float4*)(zb + 1 * (size_t)H_ + tid * 4);
    float xA0 = xb[0], xA1 = xb[1], xA2 = xb[2];
    float xB0 = xb[3], xB1 = xb[4], xB2 = xb[5];

    for (int t = 0; t < T_; t++) {
        const int buf = t & 1;

        // ---- stage A: warp-level folded reduce of pr (6 SHFL) ----
        {
            const bool k1 = !(lane & 1);
            float sA = k1 ? pr.z : pr.x;
            float rA = __shfl_xor_sync(FULL, sA, 1);
            float v0 = (k1 ? pr.x : pr.z) + rA;
            float sB = k1 ? pr.w : pr.y;
            float rB = __shfl_xor_sync(FULL, sB, 1);
            float v1 = (k1 ? pr.y : pr.w) + rB;
            const bool k2 = !(lane & 2);
            float sC = k2 ? v1 : v0;
            float rC = __shfl_xor_sync(FULL, sC, 2);
            float v  = (k2 ? v0 : v1) + rC;
            v += __shfl_xor_sync(FULL, v, 4);
            v += __shfl_xor_sync(FULL, v, 8);
            v += __shfl_xor_sync(FULL, v, 16);
            if (lane < 4) s_red[buf * NPART + warp * 4 + lane] = v;
        }

        // ---- stage B (shadow work, independent of the reduction) ----
        float base[EPT];
        {
            const float zarr[EPT] = {z0.x, z0.y, z0.z, z0.w};
#pragma unroll
            for (int e = 0; e < EPT; e++) {
                float bb = fmaf(hreg[e], DECAY_, c_bias[e]);
                bb = fmaf(zarr[e], NSTD_, bb);
                bb = fmaf(xA0, c_wi0[e], bb);
                bb = fmaf(xA1, c_wi1[e], bb);
                bb = fmaf(xA2, c_wi2[e], bb);
                base[e] = bb;
            }
        }
        const int tp = (t + 2 < T_) ? (t + 2) : (T_ - 1);
        float4 z2 = *(const float4*)(zb + (size_t)tp * H_ + tid * 4);
        const float xC0 = xb[tp * I_ + 0];
        const float xC1 = xb[tp * I_ + 1];
        const float xC2 = xb[tp * I_ + 2];

        __syncthreads();

        // ---- stage C: cross-warp reduce (LDS + 3 SHFL + 2 SHFL bcast) ----
        float Sn0, Sn1;
        {
            float u = s_red[buf * NPART + lane] + s_red[buf * NPART + 32 + lane];
            u += __shfl_xor_sync(FULL, u, 4);
            u += __shfl_xor_sync(FULL, u, 8);
            u += __shfl_xor_sync(FULL, u, 16);
            // lane&3: 0 -> n0, 1 -> wo0, 2 -> n1, 3 -> wo1
            Sn0 = __shfl_sync(FULL, u, 0);
            Sn1 = __shfl_sync(FULL, u, 2);
            if (warp == 0 && t > 0) {
                if (lane == 1) outp[(t - 1) * O_ + 0] = u;
                if (lane == 3) outp[(t - 1) * O_ + 1] = u;
            }
        }

        // ---- stage D: h_{t+1}, tanh, next pr, traj store ----
        pr = make_float4(0.f, 0.f, 0.f, 0.f);
        float hnew[EPT];
#pragma unroll
        for (int e = 0; e < EPT; e++) {
            float h = fmaf(Sn0, c_m0[e], fmaf(Sn1, c_m1[e], base[e]));
            hreg[e] = h;
            hnew[e] = h;
            float r = fast_tanh(h);
            pr.x = fmaf(r, c_n0[e], pr.x);
            pr.y = fmaf(r, c_n1[e], pr.y);
            pr.z = fmaf(r, c_wo0[e], pr.z);
            pr.w = fmaf(r, c_wo1[e], pr.w);
        }
        *(float4*)(trajp + (size_t)t * H_ + tid * 4) =
            make_float4(hnew[0], hnew[1], hnew[2], hnew[3]);

        z0 = z1; z1 = z2;
        xA0 = xB0; xA1 = xB1; xA2 = xB2;
        xB0 = xC0; xB1 = xC1; xB2 = xC2;
    }

    // ---- final reduce: out[T-1] = wo · tanh(h_T) ----
    {
        const int buf = T_ & 1;
        const bool k1 = !(lane & 1);
        float sA = k1 ? pr.z : pr.x;
        float rA = __shfl_xor_sync(FULL, sA, 1);
        float v0 = (k1 ? pr.x : pr.z) + rA;
        float sB = k1 ? pr.w : pr.y;
        float rB = __shfl_xor_sync(FULL, sB, 1);
        float v1 = (k1 ? pr.y : pr.w) + rB;
        const bool k2 = !(lane & 2);
        float sC = k2 ? v1 : v0;
        float rC = __shfl_xor_sync(FULL, sC, 2);
        float v  = (k2 ? v0 : v1) + rC;
        v += __shfl_xor_sync(FULL, v, 4);
        v += __shfl_xor_sync(FULL, v, 8);
        v += __shfl_xor_sync(FULL, v, 16);
        if (lane < 4) s_red[buf * NPART + warp * 4 + lane] = v;
        __syncthreads();
        if (warp == 0) {
            float u = s_red[buf * NPART + lane] + s_red[buf * NPART + 32 + lane];
            u += __shfl_xor_sync(FULL, u, 4);
            u += __shfl_xor_sync(FULL, u, 8);
            u += __shfl_xor_sync(FULL, u, 16);
            if (lane == 1) outp[(T_ - 1) * O_ + 0] = u;
            if (lane == 3) outp[(T_ - 1) * O_ + 1] = u;
        }
    }
}

extern "C" void kernel_launch(void* const* d_in, const int* in_sizes, int n_in,
                              void* d_out, int out_size) {
    (void)in_sizes; (void)n_in; (void)out_size;
    const float* input    = (const float*)d_in[0];
    const float* noise    = (const float*)d_in[1];
    const float* wi       = (const float*)d_in[2];
    const float* unitwi   = (const float*)d_in[3];
    const float* m        = (const float*)d_in[4];
    const float* n        = (const float*)d_in[5];
    const float* unitm    = (const float*)d_in[6];
    const float* unitn    = (const float*)d_in[7];
    const float* wo       = (const float*)d_in[8];
    const float* h0       = (const float*)d_in[9];
    const float* unith0   = (const float*)d_in[10];
    const float* bias     = (const float*)d_in[11];
    const float* gb       = (const float*)d_in[12];
    const float* uv       = (const float*)d_in[13];
    const float* sup      = (const float*)d_in[14];
    float* out            = (float*)d_out;

    lowrank_rnn_kernel<<<B_, NTHREADS>>>(input, noise, wi, unitwi, m, n, unitm,
                                         unitn, wo, h0, unith0, bias, gb, uv,
                                         sup, out);
}